// round 3
// baseline (speedup 1.0000x reference)
#include <cuda_runtime.h>
#include <cstdint>

// Instant-NGP hash grid encode, B200 (sm_100a).
// in: [524288, 3] fp32 in [-1,1]; emb: [7131219, 2] fp32; out: [524288, 32] fp32.
//
// Bottleneck (R1 ncu): L1tex wavefronts from divergent 8B gathers (88% of peak).
// Strategy:
//  1) Rebase the 13 hashed-level tables into a static buffer whose level bases
//     are even entries (16B aligned). PRIME_x==1 and hsize==2^19 mean the two
//     x-corners of a cell hash to {i, i^1} when ix is even -> one aligned
//     LDG.128 replaces two LDG.64 (halves wavefronts for those pairs).
//  2) Dense levels: x-pair is always {i, i+1}; merge when 16B-aligned.
//  3) Smem-transposed coalesced output (32 wf/stg-instr -> 4).

#define NPTS      524288u
#define HMASK     0x7FFFFu
#define PRIME_Y   2654435761u
#define PRIME_Z   805459861u
#define HASH_BASE 315475u      // c_offs[3] (first hashed level) in the original buffer
#define HASH_ENT  6815744u     // 13 levels * 524288 entries

// Rebased hashed-level tables: level l (3..15) at entry (l-3)*524288 (even -> 16B aligned).
__device__ float2 g_hash[HASH_ENT];

// ---------------------------------------------------------------------------
// Copy/rebase kernel: emb[HASH_BASE ..] -> g_hash (aligned). ~54.5 MB.
__global__ void __launch_bounds__(256)
rebase_kernel(const float2* __restrict__ emb)
{
    unsigned e = (blockIdx.x * 256u + threadIdx.x) * 2u;
    if (e < HASH_ENT) {
        float2 a = __ldg(emb + HASH_BASE + e);
        float2 b = __ldg(emb + HASH_BASE + e + 1u);
        *reinterpret_cast<float4*>(g_hash + e) = make_float4(a.x, a.y, b.x, b.y);
    }
}

// ---------------------------------------------------------------------------
__global__ void __launch_bounds__(256)
gather_kernel(const float* __restrict__ in,
              const float2* __restrict__ emb,
              float* __restrict__ out)
{
    __shared__ float s_out[256][33];   // pad 33: conflict-free column writes
    const int tid = threadIdx.x;
    const unsigned b = blockIdx.x * 256u + tid;

    const float x = (__ldg(in + 3u * b + 0u) + 1.0f) * 0.5f;
    const float y = (__ldg(in + 3u * b + 1u) + 1.0f) * 0.5f;
    const float z = (__ldg(in + 3u * b + 2u) + 1.0f) * 0.5f;

    // ---------------- dense levels 0..2 (tables 39KB / 287KB / 2.1MB) -------
    const unsigned dense_off[3] = {0u, 4913u, 40850u};
    #pragma unroll
    for (int l = 0; l < 3; ++l) {
        const unsigned res  = 16u << l;
        const unsigned r1   = res + 1u;
        const unsigned r1sq = r1 * r1;
        const unsigned off  = dense_off[l];
        const float2* __restrict__ tab = emb + off;

        const float fres = (float)res;
        const float px = x * fres, py = y * fres, pz = z * fres;
        const float gx = floorf(px), gy = floorf(py), gz = floorf(pz);
        const float tx = px - gx,   ty = py - gy,   tz = pz - gz;
        const unsigned ix = (unsigned)gx, iy = (unsigned)gy, iz = (unsigned)gz;

        const unsigned base00 = ix + iy * r1 + iz * r1sq;
        float s0 = 0.0f, s1 = 0.0f;
        #pragma unroll
        for (int yz = 0; yz < 4; ++yz) {
            const unsigned cy = (unsigned)yz & 1u;
            const unsigned cz = (unsigned)yz >> 1;
            const float wyz = (cy ? ty : 1.0f - ty) * (cz ? tz : 1.0f - tz);
            const unsigned i0 = base00 + cy * r1 + cz * r1sq;   // x-pair: i0, i0+1
            float2 v0, v1;
            if (((off + i0) & 1u) == 0u) {                      // 16B-aligned pair
                const float4 q = __ldg(reinterpret_cast<const float4*>(tab + i0));
                v0 = make_float2(q.x, q.y);
                v1 = make_float2(q.z, q.w);
            } else {
                v0 = __ldg(tab + i0);
                v1 = __ldg(tab + i0 + 1u);
            }
            s0 += wyz * (v0.x + tx * (v1.x - v0.x));
            s1 += wyz * (v0.y + tx * (v1.y - v0.y));
        }
        s_out[tid][2 * l + 0] = s0;
        s_out[tid][2 * l + 1] = s1;
    }

    // ---------------- hashed levels 3..15 (rebased tables) ------------------
    #pragma unroll 1
    for (int l = 3; l < 16; ++l) {
        const float2* __restrict__ tab = g_hash + (unsigned)(l - 3) * 524288u;

        const float fres = (float)(16u << l);
        const float px = x * fres, py = y * fres, pz = z * fres;
        const float gx = floorf(px), gy = floorf(py), gz = floorf(pz);
        const float tx = px - gx,   ty = py - gy,   tz = pz - gz;
        const unsigned ix = (unsigned)gx, iy = (unsigned)gy, iz = (unsigned)gz;

        const unsigned hy0 = iy * PRIME_Y, hy1 = hy0 + PRIME_Y;
        const unsigned hz0 = iz * PRIME_Z, hz1 = hz0 + PRIME_Z;
        const float wy0 = 1.0f - ty, wz0 = 1.0f - tz;

        float s0 = 0.0f, s1 = 0.0f;

        if ((ix & 1u) == 0u) {
            // even ix: x-pair indices are {i0, i0^1} -> one aligned LDG.128
            #pragma unroll
            for (int yz = 0; yz < 4; ++yz) {
                const unsigned cy = (unsigned)yz & 1u;
                const unsigned cz = (unsigned)yz >> 1;
                const float wyz = (cy ? ty : wy0) * (cz ? tz : wz0);
                const unsigned h  = (cy ? hy1 : hy0) ^ (cz ? hz1 : hz0);
                const unsigned i0 = (ix ^ h) & HMASK;
                const unsigned e  = i0 & ~1u;
                const float4 q = __ldg(reinterpret_cast<const float4*>(tab + e));
                const bool sw = (i0 & 1u) != 0u;   // which half is corner cx=0
                const float2 v0 = sw ? make_float2(q.z, q.w) : make_float2(q.x, q.y);
                const float2 v1 = sw ? make_float2(q.x, q.y) : make_float2(q.z, q.w);
                s0 += wyz * (v0.x + tx * (v1.x - v0.x));
                s1 += wyz * (v0.y + tx * (v1.y - v0.y));
            }
        } else {
            #pragma unroll
            for (int yz = 0; yz < 4; ++yz) {
                const unsigned cy = (unsigned)yz & 1u;
                const unsigned cz = (unsigned)yz >> 1;
                const float wyz = (cy ? ty : wy0) * (cz ? tz : wz0);
                const unsigned h  = (cy ? hy1 : hy0) ^ (cz ? hz1 : hz0);
                const unsigned i0 = (ix ^ h) & HMASK;
                const unsigned i1 = ((ix + 1u) ^ h) & HMASK;
                const float2 v0 = __ldg(tab + i0);
                const float2 v1 = __ldg(tab + i1);
                s0 += wyz * (v0.x + tx * (v1.x - v0.x));
                s1 += wyz * (v0.y + tx * (v1.y - v0.y));
            }
        }
        s_out[tid][2 * l + 0] = s0;
        s_out[tid][2 * l + 1] = s1;
    }

    __syncthreads();

    // ---------------- coalesced writeout ------------------------------------
    // Block owns out[blockIdx*256*32 .. +8192). 2048 float4s, lanes consecutive.
    float4* o4 = reinterpret_cast<float4*>(out) + (size_t)blockIdx.x * 2048u;
    #pragma unroll
    for (int r = 0; r < 8; ++r) {
        const int j  = r * 256 + tid;     // float4 index within block
        const int p  = j >> 3;            // point within block
        const int k0 = (j & 7) << 2;      // feature offset
        o4[j] = make_float4(s_out[p][k0 + 0], s_out[p][k0 + 1],
                            s_out[p][k0 + 2], s_out[p][k0 + 3]);
    }
}

// ---------------------------------------------------------------------------
extern "C" void kernel_launch(void* const* d_in, const int* in_sizes, int n_in,
                              void* d_out, int out_size)
{
    const float*  in  = (const float*)d_in[0];
    const float2* emb = (const float2*)d_in[1];
    float*        out = (float*)d_out;

    // Rebase hashed tables (must run before gather; same stream ordering).
    const unsigned copy_threads = 256u;
    const unsigned copy_blocks  = (HASH_ENT / 2u + copy_threads - 1u) / copy_threads;
    rebase_kernel<<<copy_blocks, copy_threads>>>(emb);

    gather_kernel<<<NPTS / 256u, 256u>>>(in, emb, out);
}